// round 15
// baseline (speedup 1.0000x reference)
#include <cuda_runtime.h>
#include <cuda_fp16.h>
#include <cstdint>
#include <cstddef>

#define FEAT 128
#define NUM_BASES 4
#define NCT 5
#define MAX_NODES 100000
#define MAX_EDGES 1000000
#define PROJ_STRIDE (NUM_BASES * FEAT)   // 512 halfs per node
#define BSHIFT 5                          // 32 nodes per bucket
#define NBKT 3200                         // >= 100000/32 = 3125

typedef unsigned int u32;

// scratch
__device__ __half g_projh[(size_t)MAX_NODES * PROJ_STRIDE];
__device__ __half g_wth[NCT * FEAT * FEAT];   // [ct][n][k] = fp16(W_ct[k][n])
__device__ int    g_cnt[NBKT + 1];
__device__ int    g_off[NBKT + 1];
__device__ int    g_pos[NBKT + 1];
__device__ int    g_pk[MAX_EDGES];            // (src<<3)|rel, bucket-sorted
__device__ int    g_pd[MAX_EDGES];            // dst, bucket-sorted

__device__ __forceinline__ void mma_f16(float* d, const u32* a, const u32* b) {
    asm("mma.sync.aligned.m16n8k16.row.col.f32.f16.f16.f32 "
        "{%0,%1,%2,%3}, {%4,%5,%6,%7}, {%8,%9}, {%0,%1,%2,%3};"
        : "+f"(d[0]), "+f"(d[1]), "+f"(d[2]), "+f"(d[3])
        : "r"(a[0]), "r"(a[1]), "r"(a[2]), "r"(a[3]), "r"(b[0]), "r"(b[1]));
}
__device__ __forceinline__ u32 smem_u32(const void* p) {
    u32 a;
    asm("{ .reg .u64 t; cvta.to.shared.u64 t, %1; cvt.u32.u64 %0, t; }" : "=r"(a) : "l"(p));
    return a;
}
__device__ __forceinline__ void ldsm4(u32& r0, u32& r1, u32& r2, u32& r3, u32 addr) {
    asm volatile("ldmatrix.sync.aligned.m8n8.x4.shared.b16 {%0,%1,%2,%3}, [%4];"
                 : "=r"(r0), "=r"(r1), "=r"(r2), "=r"(r3) : "r"(addr));
}
__device__ __forceinline__ void red_add_v4(float* ptr, float a, float b, float c, float d) {
    asm volatile("red.global.add.v4.f32 [%0], {%1, %2, %3, %4};"
                 :: "l"(ptr), "f"(a), "f"(b), "f"(c), "f"(d) : "memory");
}
__device__ __forceinline__ void cpa16(u32 dst, const void* src) {
    asm volatile("cp.async.ca.shared.global [%0], [%1], 16;" :: "r"(dst), "l"(src));
}
#define CPA_COMMIT() asm volatile("cp.async.commit_group;" ::: "memory")
#define CPA_WAIT(n)  asm volatile("cp.async.wait_group %0;" :: "n"(n) : "memory")

// ---------------- kernel 0: transpose weights into fp16 g_wth ----------------
__global__ void transpose_w_kernel(const float* __restrict__ weight,
                                   const float* __restrict__ root)
{
    __shared__ float tile[32][33];
    const int ct = blockIdx.z;
    const float* __restrict__ src = (ct < NUM_BASES) ? (weight + (size_t)ct * FEAT * FEAT)
                                                     : root;
    const int n0 = blockIdx.x * 32, k0 = blockIdx.y * 32;
    const int tx = threadIdx.x, ty = threadIdx.y;  // 32 x 8
#pragma unroll
    for (int j = 0; j < 32; j += 8)
        tile[ty + j][tx] = src[(size_t)(k0 + ty + j) * FEAT + n0 + tx];
    __syncthreads();
    __half* __restrict__ dst = g_wth + (size_t)ct * FEAT * FEAT;
#pragma unroll
    for (int j = 0; j < 32; j += 8)
        dst[(size_t)(n0 + ty + j) * FEAT + k0 + tx] = __float2half_rn(tile[tx][ty + j]);
}

// ---------------- edge bucket sort (by src >> BSHIFT) ----------------
__global__ void zero_cnt_kernel(int nb)
{
    int i = blockIdx.x * blockDim.x + threadIdx.x;
    if (i <= nb) g_cnt[i] = 0;
}
__global__ void hist_kernel(const int* __restrict__ src, int n_edges)
{
    int i = blockIdx.x * blockDim.x + threadIdx.x;
    if (i < n_edges) atomicAdd(&g_cnt[src[i] >> BSHIFT], 1);
}
// single-block carry scan (exclusive) over nb+1 entries
__global__ void scan_kernel(int n)
{
    __shared__ int tmp[1024];
    const int t = threadIdx.x;
    int carry = 0;
    for (int base = 0; base < n; base += 1024) {
        const int i = base + t;
        const int v = (i < n) ? g_cnt[i] : 0;
        tmp[t] = v;
        __syncthreads();
        for (int d = 1; d < 1024; d <<= 1) {
            int x = (t >= d) ? tmp[t - d] : 0;
            __syncthreads();
            tmp[t] += x;
            __syncthreads();
        }
        if (i < n) {
            const int excl = carry + tmp[t] - v;
            g_off[i] = excl;
            g_pos[i] = excl;
        }
        carry += tmp[1023];
        __syncthreads();
    }
}
__global__ void scatter_kernel(const int* __restrict__ src,
                               const int* __restrict__ dst,
                               const int* __restrict__ rel, int n_edges)
{
    int i = blockIdx.x * blockDim.x + threadIdx.x;
    if (i >= n_edges) return;
    const int s = src[i];
    const int pos = atomicAdd(&g_pos[s >> BSHIFT], 1);
    g_pk[pos] = (s << 3) | rel[i];
    g_pd[pos] = dst[i];
}

// ---------------- kernel 1: fp16 mma GEMM (R13: 256 thr, A-resident, ct-loop) ----------------
#define PADH 136
#define TILE_H (128 * PADH)
#define SM_TOTALB (3 * TILE_H * 2)    // 104448 B

__global__ void __launch_bounds__(256, 2)
rgcn_gemm_mma_kernel(const float* __restrict__ h,
                     const float* __restrict__ bias,
                     float* __restrict__ out, int n_nodes)
{
    extern __shared__ __half smemh[];
    __half* As = smemh;

    const int tid  = threadIdx.x;
    const int lane = tid & 31;
    const int w    = tid >> 5;
    const int g    = lane >> 2;
    const int tig  = lane & 3;
    const int warp_m = w & 3;
    const int warp_n = w >> 2;

    const int row0 = blockIdx.x * 128;

    const int l_row = lane & 15;
    const int l_kd  = (lane >> 4) * 8;

    const u32 sA = smem_u32(As);
    const u32 sB0 = sA + TILE_H * 2;
    const u32 sB1 = sA + 2 * TILE_H * 2;

#pragma unroll
    for (int i = 0; i < 16; i++) {
        const int v  = tid + i * 256;
        const int r  = v >> 5;
        const int c4 = (v & 31) * 4;
        float4 av = make_float4(0.f, 0.f, 0.f, 0.f);
        const int gr = row0 + r;
        if (gr < n_nodes)
            av = *(const float4*)(h + (size_t)gr * FEAT + c4);
        __half2 a01 = __floats2half2_rn(av.x, av.y);
        __half2 a23 = __floats2half2_rn(av.z, av.w);
        *(uint2*)(As + r * PADH + c4) = make_uint2(*(u32*)&a01, *(u32*)&a23);
    }

    auto issue_b = [&](int ct, u32 sBdst) {
        const __half* __restrict__ src = g_wth + (size_t)ct * FEAT * FEAT;
#pragma unroll
        for (int i = 0; i < 8; i++) {
            const int v  = tid + i * 256;
            const int r  = v >> 4;
            const int c8 = (v & 15) * 8;
            cpa16(sBdst + (u32)((r * PADH + c8) * 2), src + (size_t)r * FEAT + c8);
        }
        CPA_COMMIT();
    };

    issue_b(0, sB0);

    float acc[2][8][4];
#pragma unroll
    for (int mi = 0; mi < 2; mi++)
#pragma unroll
        for (int j = 0; j < 8; j++)
#pragma unroll
            for (int c = 0; c < 4; c++) acc[mi][j][c] = 0.f;

#pragma unroll 1
    for (int ct = 0; ct < NCT; ct++) {
        if (ct + 1 < NCT) {
            issue_b(ct + 1, ((ct + 1) & 1) ? sB1 : sB0);
            CPA_WAIT(1);
        } else {
            CPA_WAIT(0);
        }
        __syncthreads();
        const u32 sB = (ct & 1) ? sB1 : sB0;

#pragma unroll
        for (int ks = 0; ks < 8; ks++) {
            const int kk = ks * 16;
            u32 af[2][4];
#pragma unroll
            for (int mi = 0; mi < 2; mi++) {
                const u32 off = (u32)(((warp_m * 32 + mi * 16 + l_row) * PADH
                                       + kk + l_kd) * 2);
                ldsm4(af[mi][0], af[mi][1], af[mi][2], af[mi][3], sA + off);
            }
            u32 bf[8][2];
#pragma unroll
            for (int jp = 0; jp < 4; jp++) {
                const u32 off = (u32)(((warp_n * 64 + jp * 16 + l_row) * PADH
                                       + kk + l_kd) * 2);
                u32 m0, m1, m2, m3;
                ldsm4(m0, m1, m2, m3, sB + off);
                bf[2 * jp][0] = m0;     bf[2 * jp][1] = m2;
                bf[2 * jp + 1][0] = m1; bf[2 * jp + 1][1] = m3;
            }
#pragma unroll
            for (int mi = 0; mi < 2; mi++)
#pragma unroll
                for (int j = 0; j < 8; j++)
                    mma_f16(acc[mi][j], af[mi], bf[j]);
        }
        __syncthreads();

#pragma unroll
        for (int mi = 0; mi < 2; mi++) {
#pragma unroll
            for (int half = 0; half < 2; half++) {
                const int grow = row0 + warp_m * 32 + mi * 16 + g + half * 8;
                if (grow < n_nodes) {
                    if (ct < NUM_BASES) {
                        __half* p = g_projh + (size_t)grow * PROJ_STRIDE + ct * FEAT
                                  + warp_n * 64 + 2 * tig;
#pragma unroll
                        for (int j = 0; j < 8; j++)
                            *(__half2*)(p + 8 * j) =
                                __floats2half2_rn(acc[mi][j][2 * half],
                                                  acc[mi][j][2 * half + 1]);
                    } else {
                        float* p = out + (size_t)grow * FEAT + warp_n * 64 + 2 * tig;
#pragma unroll
                        for (int j = 0; j < 8; j++) {
                            const float2 b =
                                *(const float2*)(bias + warp_n * 64 + 2 * tig + 8 * j);
                            *(float2*)(p + 8 * j) =
                                make_float2(acc[mi][j][2 * half] + b.x,
                                            acc[mi][j][2 * half + 1] + b.y);
                        }
                    }
                }
            }
        }
#pragma unroll
        for (int mi = 0; mi < 2; mi++)
#pragma unroll
            for (int j = 0; j < 8; j++)
#pragma unroll
                for (int c = 0; c < 4; c++) acc[mi][j][c] = 0.f;
    }
}

// ---------------- kernel 2: bucketed edge kernel, smem-staged gather ----------------
// One block per 32-node src bucket: stage 32 proj rows (32 KB) once, then warps
// process the bucket's edges from smem; vector red to out[dst].
__global__ void __launch_bounds__(256)
rgcn_edge_kernel(const float* __restrict__ w_comp, float* __restrict__ out)
{
    __shared__ __half staged[32 * PROJ_STRIDE];   // 32 KB
    __shared__ float  wc[NUM_BASES * 8];          // 8 relations x 4

    const int bkt = blockIdx.x;
    const int tid = threadIdx.x;
    const int lane = tid & 31;
    const int wib  = tid >> 5;        // warp in block, 0..7

    if (tid < 32) wc[tid] = w_comp[tid];

    // stage: 32 rows x 1KB = 2048 uint4, 8 per thread (coalesced)
    {
        const uint4* __restrict__ gsrc =
            (const uint4*)(g_projh + (size_t)bkt * 32 * PROJ_STRIDE);
        uint4* __restrict__ sdst = (uint4*)staged;
#pragma unroll
        for (int i = 0; i < 8; i++)
            sdst[tid + i * 256] = gsrc[tid + i * 256];
    }
    const int beg = g_off[bkt];
    const int end = g_off[bkt + 1];
    __syncthreads();

    for (int e = beg + wib; e < end; e += 8) {
        const int pk = g_pk[e];
        const int d  = g_pd[e];
        const int sl = (pk >> 3) & 31;   // src local to bucket
        const int r  = pk & 7;
        const float4 c = *(const float4*)(wc + r * NUM_BASES);

        const uint2* __restrict__ p =
            (const uint2*)(staged + (size_t)sl * PROJ_STRIDE) + lane;
        float m0 = 0.f, m1 = 0.f, m2 = 0.f, m3 = 0.f;
#pragma unroll
        for (int b = 0; b < 4; b++) {
            const float cb = (&c.x)[b];
            const uint2 raw = p[b * 32];
            const float2 v0 = __half22float2(*(const __half2*)&raw.x);
            const float2 v1 = __half22float2(*(const __half2*)&raw.y);
            m0 = fmaf(cb, v0.x, m0);
            m1 = fmaf(cb, v0.y, m1);
            m2 = fmaf(cb, v1.x, m2);
            m3 = fmaf(cb, v1.y, m3);
        }
        red_add_v4(out + (size_t)d * FEAT + 4 * lane, m0, m1, m2, m3);
    }
}

__global__ void rgcn_relu_kernel(float* __restrict__ out, int n4)
{
    int i = blockIdx.x * blockDim.x + threadIdx.x;
    if (i < n4) {
        float4 v = ((float4*)out)[i];
        v.x = fmaxf(v.x, 0.f); v.y = fmaxf(v.y, 0.f);
        v.z = fmaxf(v.z, 0.f); v.w = fmaxf(v.w, 0.f);
        ((float4*)out)[i] = v;
    }
}

extern "C" void kernel_launch(void* const* d_in, const int* in_sizes, int n_in,
                              void* d_out, int out_size)
{
    const float* h      = (const float*)d_in[0];
    const float* weight = (const float*)d_in[1];
    const float* w_comp = (const float*)d_in[2];
    const float* root   = (const float*)d_in[3];
    const float* bias   = (const float*)d_in[4];
    const int*   src    = (const int*)d_in[5];
    const int*   dst    = (const int*)d_in[6];
    const int*   rel    = (const int*)d_in[7];

    const int n_nodes = in_sizes[0] / FEAT;
    const int n_edges = in_sizes[5];
    const int n_bkt   = (n_nodes + 31) >> BSHIFT;
    float* out = (float*)d_out;

    cudaFuncSetAttribute(rgcn_gemm_mma_kernel,
                         cudaFuncAttributeMaxDynamicSharedMemorySize, SM_TOTALB);

    // 0) weight transpose + edge bucket sort (tiny kernels)
    dim3 gt(4, 4, NCT);
    transpose_w_kernel<<<gt, dim3(32, 8)>>>(weight, root);
    zero_cnt_kernel<<<(n_bkt + 256) / 256, 256>>>(n_bkt);
    hist_kernel<<<(n_edges + 255) / 256, 256>>>(src, n_edges);
    scan_kernel<<<1, 1024>>>(n_bkt + 1);
    scatter_kernel<<<(n_edges + 255) / 256, 256>>>(src, dst, rel, n_edges);

    // 1) fp16 GEMM, A resident, ct loop
    rgcn_gemm_mma_kernel<<<(n_nodes + 127) / 128, 256, SM_TOTALB>>>(h, bias, out, n_nodes);

    // 2) bucketed edge combine + vector scatter-add
    rgcn_edge_kernel<<<n_bkt, 256>>>(w_comp, out);

    // 3) ReLU
    int n4 = out_size / 4;
    rgcn_relu_kernel<<<(n4 + 255) / 256, 256>>>(out, n4);
}

// round 16
// speedup vs baseline: 1.2180x; 1.2180x over previous
#include <cuda_runtime.h>
#include <cuda_fp16.h>
#include <cstdint>
#include <cstddef>

#define FEAT 128
#define NUM_BASES 4
#define NCT 5
#define MAX_NODES 100000
#define MAX_EDGES 1000000
#define PROJ_STRIDE (NUM_BASES * FEAT)   // 512 halfs per node
#define NCHUNK 128                        // >= ceil((MAX_NODES+1)/1024)

typedef unsigned int u32;

// scratch
__device__ __half g_projh[(size_t)MAX_NODES * PROJ_STRIDE];
__device__ __half g_wth[NCT * FEAT * FEAT];   // [ct][n][k] = fp16(W_ct[k][n])
__device__ int    g_cnt[MAX_NODES + 2];
__device__ int    g_off[MAX_NODES + 2];
__device__ int    g_pos[MAX_NODES + 2];
__device__ int    g_bsum[NCHUNK];
__device__ int    g_pk[MAX_EDGES];            // (src<<3)|rel, dst-CSR order

__device__ __forceinline__ void mma_f16(float* d, const u32* a, const u32* b) {
    asm("mma.sync.aligned.m16n8k16.row.col.f32.f16.f16.f32 "
        "{%0,%1,%2,%3}, {%4,%5,%6,%7}, {%8,%9}, {%0,%1,%2,%3};"
        : "+f"(d[0]), "+f"(d[1]), "+f"(d[2]), "+f"(d[3])
        : "r"(a[0]), "r"(a[1]), "r"(a[2]), "r"(a[3]), "r"(b[0]), "r"(b[1]));
}
__device__ __forceinline__ u32 smem_u32(const void* p) {
    u32 a;
    asm("{ .reg .u64 t; cvta.to.shared.u64 t, %1; cvt.u32.u64 %0, t; }" : "=r"(a) : "l"(p));
    return a;
}
__device__ __forceinline__ void ldsm4(u32& r0, u32& r1, u32& r2, u32& r3, u32 addr) {
    asm volatile("ldmatrix.sync.aligned.m8n8.x4.shared.b16 {%0,%1,%2,%3}, [%4];"
                 : "=r"(r0), "=r"(r1), "=r"(r2), "=r"(r3) : "r"(addr));
}
__device__ __forceinline__ void cpa16(u32 dst, const void* src) {
    asm volatile("cp.async.ca.shared.global [%0], [%1], 16;" :: "r"(dst), "l"(src));
}
#define CPA_COMMIT() asm volatile("cp.async.commit_group;" ::: "memory")
#define CPA_WAIT(n)  asm volatile("cp.async.wait_group %0;" :: "n"(n) : "memory")

// ---------------- kernel 0: transpose weights into fp16 g_wth ----------------
__global__ void transpose_w_kernel(const float* __restrict__ weight,
                                   const float* __restrict__ root)
{
    __shared__ float tile[32][33];
    const int ct = blockIdx.z;
    const float* __restrict__ src = (ct < NUM_BASES) ? (weight + (size_t)ct * FEAT * FEAT)
                                                     : root;
    const int n0 = blockIdx.x * 32, k0 = blockIdx.y * 32;
    const int tx = threadIdx.x, ty = threadIdx.y;  // 32 x 8
#pragma unroll
    for (int j = 0; j < 32; j += 8)
        tile[ty + j][tx] = src[(size_t)(k0 + ty + j) * FEAT + n0 + tx];
    __syncthreads();
    __half* __restrict__ dst = g_wth + (size_t)ct * FEAT * FEAT;
#pragma unroll
    for (int j = 0; j < 32; j += 8)
        dst[(size_t)(n0 + ty + j) * FEAT + k0 + tx] = __float2half_rn(tile[tx][ty + j]);
}

// ---------------- dst-CSR build: zero/hist/3-level scan/scatter ----------------
__global__ void zero_cnt_kernel(int n)
{
    int i = blockIdx.x * blockDim.x + threadIdx.x;
    if (i <= n) g_cnt[i] = 0;
}
__global__ void hist_kernel(const int* __restrict__ dst, int n_edges)
{
    int i = blockIdx.x * blockDim.x + threadIdx.x;
    if (i < n_edges) atomicAdd(&g_cnt[dst[i]], 1);
}
// per-chunk exclusive scan (1024 entries per block) + chunk totals
__global__ void scan_chunk_kernel(int n)
{
    __shared__ int tmp[1024];
    const int t = threadIdx.x;
    const int i = blockIdx.x * 1024 + t;
    const int v = (i < n) ? g_cnt[i] : 0;
    tmp[t] = v;
    __syncthreads();
    for (int d = 1; d < 1024; d <<= 1) {
        int x = (t >= d) ? tmp[t - d] : 0;
        __syncthreads();
        tmp[t] += x;
        __syncthreads();
    }
    if (i < n) g_off[i] = tmp[t] - v;       // chunk-local exclusive
    if (t == 1023) g_bsum[blockIdx.x] = tmp[1023];
}
// scan chunk totals (single block)
__global__ void scan_bsum_kernel(int nb)
{
    __shared__ int tmp[NCHUNK];
    const int t = threadIdx.x;
    const int v = (t < nb) ? g_bsum[t] : 0;
    tmp[t] = v;
    __syncthreads();
    for (int d = 1; d < NCHUNK; d <<= 1) {
        int x = (t >= d) ? tmp[t - d] : 0;
        __syncthreads();
        tmp[t] += x;
        __syncthreads();
    }
    if (t < nb) g_bsum[t] = tmp[t] - v;     // exclusive
}
// add chunk offsets; fill g_pos
__global__ void scan_add_kernel(int n)
{
    int i = blockIdx.x * blockDim.x + threadIdx.x;
    if (i < n) {
        const int off = g_off[i] + g_bsum[i >> 10];
        g_off[i] = off;
        g_pos[i] = off;
    }
}
__global__ void scatter_kernel(const int* __restrict__ src,
                               const int* __restrict__ dst,
                               const int* __restrict__ rel, int n_edges)
{
    int i = blockIdx.x * blockDim.x + threadIdx.x;
    if (i >= n_edges) return;
    const int pos = atomicAdd(&g_pos[dst[i]], 1);
    g_pk[pos] = (src[i] << 3) | rel[i];
}

// ---------------- kernel 1: fp16 mma GEMM (R13: 256 thr, A-resident, ct-loop) ----------------
#define PADH 136
#define TILE_H (128 * PADH)
#define SM_TOTALB (3 * TILE_H * 2)    // 104448 B

__global__ void __launch_bounds__(256, 2)
rgcn_gemm_mma_kernel(const float* __restrict__ h,
                     const float* __restrict__ bias,
                     float* __restrict__ out, int n_nodes)
{
    extern __shared__ __half smemh[];
    __half* As = smemh;

    const int tid  = threadIdx.x;
    const int lane = tid & 31;
    const int w    = tid >> 5;
    const int g    = lane >> 2;
    const int tig  = lane & 3;
    const int warp_m = w & 3;
    const int warp_n = w >> 2;

    const int row0 = blockIdx.x * 128;

    const int l_row = lane & 15;
    const int l_kd  = (lane >> 4) * 8;

    const u32 sA = smem_u32(As);
    const u32 sB0 = sA + TILE_H * 2;
    const u32 sB1 = sA + 2 * TILE_H * 2;

#pragma unroll
    for (int i = 0; i < 16; i++) {
        const int v  = tid + i * 256;
        const int r  = v >> 5;
        const int c4 = (v & 31) * 4;
        float4 av = make_float4(0.f, 0.f, 0.f, 0.f);
        const int gr = row0 + r;
        if (gr < n_nodes)
            av = *(const float4*)(h + (size_t)gr * FEAT + c4);
        __half2 a01 = __floats2half2_rn(av.x, av.y);
        __half2 a23 = __floats2half2_rn(av.z, av.w);
        *(uint2*)(As + r * PADH + c4) = make_uint2(*(u32*)&a01, *(u32*)&a23);
    }

    auto issue_b = [&](int ct, u32 sBdst) {
        const __half* __restrict__ src = g_wth + (size_t)ct * FEAT * FEAT;
#pragma unroll
        for (int i = 0; i < 8; i++) {
            const int v  = tid + i * 256;
            const int r  = v >> 4;
            const int c8 = (v & 15) * 8;
            cpa16(sBdst + (u32)((r * PADH + c8) * 2), src + (size_t)r * FEAT + c8);
        }
        CPA_COMMIT();
    };

    issue_b(0, sB0);

    float acc[2][8][4];
#pragma unroll
    for (int mi = 0; mi < 2; mi++)
#pragma unroll
        for (int j = 0; j < 8; j++)
#pragma unroll
            for (int c = 0; c < 4; c++) acc[mi][j][c] = 0.f;

#pragma unroll 1
    for (int ct = 0; ct < NCT; ct++) {
        if (ct + 1 < NCT) {
            issue_b(ct + 1, ((ct + 1) & 1) ? sB1 : sB0);
            CPA_WAIT(1);
        } else {
            CPA_WAIT(0);
        }
        __syncthreads();
        const u32 sB = (ct & 1) ? sB1 : sB0;

#pragma unroll
        for (int ks = 0; ks < 8; ks++) {
            const int kk = ks * 16;
            u32 af[2][4];
#pragma unroll
            for (int mi = 0; mi < 2; mi++) {
                const u32 off = (u32)(((warp_m * 32 + mi * 16 + l_row) * PADH
                                       + kk + l_kd) * 2);
                ldsm4(af[mi][0], af[mi][1], af[mi][2], af[mi][3], sA + off);
            }
            u32 bf[8][2];
#pragma unroll
            for (int jp = 0; jp < 4; jp++) {
                const u32 off = (u32)(((warp_n * 64 + jp * 16 + l_row) * PADH
                                       + kk + l_kd) * 2);
                u32 m0, m1, m2, m3;
                ldsm4(m0, m1, m2, m3, sB + off);
                bf[2 * jp][0] = m0;     bf[2 * jp][1] = m2;
                bf[2 * jp + 1][0] = m1; bf[2 * jp + 1][1] = m3;
            }
#pragma unroll
            for (int mi = 0; mi < 2; mi++)
#pragma unroll
                for (int j = 0; j < 8; j++)
                    mma_f16(acc[mi][j], af[mi], bf[j]);
        }
        __syncthreads();

#pragma unroll
        for (int mi = 0; mi < 2; mi++) {
#pragma unroll
            for (int half = 0; half < 2; half++) {
                const int grow = row0 + warp_m * 32 + mi * 16 + g + half * 8;
                if (grow < n_nodes) {
                    if (ct < NUM_BASES) {
                        __half* p = g_projh + (size_t)grow * PROJ_STRIDE + ct * FEAT
                                  + warp_n * 64 + 2 * tig;
#pragma unroll
                        for (int j = 0; j < 8; j++)
                            *(__half2*)(p + 8 * j) =
                                __floats2half2_rn(acc[mi][j][2 * half],
                                                  acc[mi][j][2 * half + 1]);
                    } else {
                        float* p = out + (size_t)grow * FEAT + warp_n * 64 + 2 * tig;
#pragma unroll
                        for (int j = 0; j < 8; j++) {
                            const float2 b =
                                *(const float2*)(bias + warp_n * 64 + 2 * tig + 8 * j);
                            *(float2*)(p + 8 * j) =
                                make_float2(acc[mi][j][2 * half] + b.x,
                                            acc[mi][j][2 * half + 1] + b.y);
                        }
                    }
                }
            }
        }
#pragma unroll
        for (int mi = 0; mi < 2; mi++)
#pragma unroll
            for (int j = 0; j < 8; j++)
#pragma unroll
                for (int c = 0; c < 4; c++) acc[mi][j][c] = 0.f;
    }
}

// ---------------- kernel 2: warp-per-dst aggregation, atomic-free, fused ReLU ----------------
__global__ void __launch_bounds__(256)
rgcn_agg_kernel(const float* __restrict__ w_comp,
                float* __restrict__ out, int n_nodes)
{
    const int node = (blockIdx.x * blockDim.x + threadIdx.x) >> 5;
    const int lane = threadIdx.x & 31;
    if (node >= n_nodes) return;

    const int beg = g_off[node];
    const int end = g_off[node + 1];

    float* __restrict__ orow = out + (size_t)node * FEAT;
    float4 a = *(float4*)(orow + 4 * lane);   // root + bias from GEMM

    int e = beg;
    for (; e + 2 <= end; e += 2) {
        const int pk0 = g_pk[e], pk1 = g_pk[e + 1];
        const uint2* __restrict__ p0 =
            (const uint2*)(g_projh + (size_t)(pk0 >> 3) * PROJ_STRIDE) + lane;
        const uint2* __restrict__ p1 =
            (const uint2*)(g_projh + (size_t)(pk1 >> 3) * PROJ_STRIDE) + lane;
        const float4 c0 = *(const float4*)(w_comp + (pk0 & 7) * NUM_BASES);
        const float4 c1 = *(const float4*)(w_comp + (pk1 & 7) * NUM_BASES);
        uint2 r0[4], r1[4];
#pragma unroll
        for (int b = 0; b < 4; b++) { r0[b] = p0[b * 32]; r1[b] = p1[b * 32]; }
#pragma unroll
        for (int b = 0; b < 4; b++) {
            const float cb0 = (&c0.x)[b];
            const float2 u0 = __half22float2(*(const __half2*)&r0[b].x);
            const float2 u1 = __half22float2(*(const __half2*)&r0[b].y);
            a.x = fmaf(cb0, u0.x, a.x);
            a.y = fmaf(cb0, u0.y, a.y);
            a.z = fmaf(cb0, u1.x, a.z);
            a.w = fmaf(cb0, u1.y, a.w);
            const float cb1 = (&c1.x)[b];
            const float2 v0 = __half22float2(*(const __half2*)&r1[b].x);
            const float2 v1 = __half22float2(*(const __half2*)&r1[b].y);
            a.x = fmaf(cb1, v0.x, a.x);
            a.y = fmaf(cb1, v0.y, a.y);
            a.z = fmaf(cb1, v1.x, a.z);
            a.w = fmaf(cb1, v1.y, a.w);
        }
    }
    if (e < end) {
        const int pk = g_pk[e];
        const uint2* __restrict__ p =
            (const uint2*)(g_projh + (size_t)(pk >> 3) * PROJ_STRIDE) + lane;
        const float4 c = *(const float4*)(w_comp + (pk & 7) * NUM_BASES);
#pragma unroll
        for (int b = 0; b < 4; b++) {
            const float cb = (&c.x)[b];
            const uint2 raw = p[b * 32];
            const float2 u0 = __half22float2(*(const __half2*)&raw.x);
            const float2 u1 = __half22float2(*(const __half2*)&raw.y);
            a.x = fmaf(cb, u0.x, a.x);
            a.y = fmaf(cb, u0.y, a.y);
            a.z = fmaf(cb, u1.x, a.z);
            a.w = fmaf(cb, u1.y, a.w);
        }
    }

    a.x = fmaxf(a.x, 0.f); a.y = fmaxf(a.y, 0.f);
    a.z = fmaxf(a.z, 0.f); a.w = fmaxf(a.w, 0.f);
    *(float4*)(orow + 4 * lane) = a;
}

extern "C" void kernel_launch(void* const* d_in, const int* in_sizes, int n_in,
                              void* d_out, int out_size)
{
    const float* h      = (const float*)d_in[0];
    const float* weight = (const float*)d_in[1];
    const float* w_comp = (const float*)d_in[2];
    const float* root   = (const float*)d_in[3];
    const float* bias   = (const float*)d_in[4];
    const int*   src    = (const int*)d_in[5];
    const int*   dst    = (const int*)d_in[6];
    const int*   rel    = (const int*)d_in[7];

    const int n_nodes = in_sizes[0] / FEAT;
    const int n_edges = in_sizes[5];
    const int n_scan  = n_nodes + 1;
    const int n_chunk = (n_scan + 1023) / 1024;
    float* out = (float*)d_out;

    cudaFuncSetAttribute(rgcn_gemm_mma_kernel,
                         cudaFuncAttributeMaxDynamicSharedMemorySize, SM_TOTALB);

    // 0) weight transpose + dst-CSR build (hierarchical scan)
    dim3 gt(4, 4, NCT);
    transpose_w_kernel<<<gt, dim3(32, 8)>>>(weight, root);
    zero_cnt_kernel<<<(n_nodes + 256) / 256, 256>>>(n_nodes);
    hist_kernel<<<(n_edges + 255) / 256, 256>>>(dst, n_edges);
    scan_chunk_kernel<<<n_chunk, 1024>>>(n_scan);
    scan_bsum_kernel<<<1, NCHUNK>>>(n_chunk);
    scan_add_kernel<<<(n_scan + 255) / 256, 256>>>(n_scan);
    scatter_kernel<<<(n_edges + 255) / 256, 256>>>(src, dst, rel, n_edges);

    // 1) fp16 GEMM, A resident, ct loop (proj fp16 + root/bias fp32 into out)
    rgcn_gemm_mma_kernel<<<(n_nodes + 127) / 128, 256, SM_TOTALB>>>(h, bias, out, n_nodes);

    // 2) warp-per-dst aggregation + fused ReLU (no atomics)
    rgcn_agg_kernel<<<(n_nodes + 7) / 8, 256>>>(w_comp, out, n_nodes);
}

// round 17
// speedup vs baseline: 1.2827x; 1.0532x over previous
#include <cuda_runtime.h>
#include <cuda_fp16.h>
#include <cstdint>
#include <cstddef>

#define FEAT 128
#define NUM_BASES 4
#define NCT 5
#define MAX_NODES 100000
#define MAX_EDGES 1000000
#define PROJ_STRIDE (NUM_BASES * FEAT)   // 512 halfs per node
#define NCHUNK 128                        // >= ceil((MAX_NODES+1)/1024)

typedef unsigned int u32;

// scratch
__device__ __half g_projh[(size_t)MAX_NODES * PROJ_STRIDE];
__device__ __half g_wth[NCT * FEAT * FEAT];   // [ct][n][k] = fp16(W_ct[k][n])
__device__ int    g_cnt[MAX_NODES + 2];       // zero-initialized; self-zeroing
__device__ int    g_off[MAX_NODES + 2];
__device__ int    g_pos[MAX_NODES + 2];
__device__ int    g_bsum[NCHUNK];
__device__ int    g_pk[MAX_EDGES];            // (src<<3)|rel, dst-CSR order

__device__ __forceinline__ void mma_f16(float* d, const u32* a, const u32* b) {
    asm("mma.sync.aligned.m16n8k16.row.col.f32.f16.f16.f32 "
        "{%0,%1,%2,%3}, {%4,%5,%6,%7}, {%8,%9}, {%0,%1,%2,%3};"
        : "+f"(d[0]), "+f"(d[1]), "+f"(d[2]), "+f"(d[3])
        : "r"(a[0]), "r"(a[1]), "r"(a[2]), "r"(a[3]), "r"(b[0]), "r"(b[1]));
}
__device__ __forceinline__ u32 smem_u32(const void* p) {
    u32 a;
    asm("{ .reg .u64 t; cvta.to.shared.u64 t, %1; cvt.u32.u64 %0, t; }" : "=r"(a) : "l"(p));
    return a;
}
__device__ __forceinline__ void ldsm4(u32& r0, u32& r1, u32& r2, u32& r3, u32 addr) {
    asm volatile("ldmatrix.sync.aligned.m8n8.x4.shared.b16 {%0,%1,%2,%3}, [%4];"
                 : "=r"(r0), "=r"(r1), "=r"(r2), "=r"(r3) : "r"(addr));
}
__device__ __forceinline__ void cpa16(u32 dst, const void* src) {
    asm volatile("cp.async.ca.shared.global [%0], [%1], 16;" :: "r"(dst), "l"(src));
}
#define CPA_COMMIT() asm volatile("cp.async.commit_group;" ::: "memory")
#define CPA_WAIT(n)  asm volatile("cp.async.wait_group %0;" :: "n"(n) : "memory")

// ---------------- kernel 0: transpose weights into fp16 g_wth ----------------
__global__ void transpose_w_kernel(const float* __restrict__ weight,
                                   const float* __restrict__ root)
{
    __shared__ float tile[32][33];
    const int ct = blockIdx.z;
    const float* __restrict__ src = (ct < NUM_BASES) ? (weight + (size_t)ct * FEAT * FEAT)
                                                     : root;
    const int n0 = blockIdx.x * 32, k0 = blockIdx.y * 32;
    const int tx = threadIdx.x, ty = threadIdx.y;  // 32 x 8
#pragma unroll
    for (int j = 0; j < 32; j += 8)
        tile[ty + j][tx] = src[(size_t)(k0 + ty + j) * FEAT + n0 + tx];
    __syncthreads();
    __half* __restrict__ dst = g_wth + (size_t)ct * FEAT * FEAT;
#pragma unroll
    for (int j = 0; j < 32; j += 8)
        dst[(size_t)(n0 + ty + j) * FEAT + k0 + tx] = __float2half_rn(tile[tx][ty + j]);
}

// ---------------- dst-CSR build (side stream) ----------------
__global__ void hist_kernel(const int* __restrict__ dst, int n_edges)
{
    int i = blockIdx.x * blockDim.x + threadIdx.x;
    if (i < n_edges) atomicAdd(&g_cnt[dst[i]], 1);
}
// per-chunk exclusive scan via warp shuffles; self-zeroes g_cnt for next replay
__global__ void scan_chunk_kernel(int n)
{
    __shared__ int wsum[32];
    const int t = threadIdx.x;
    const int i = blockIdx.x * 1024 + t;
    const int lane = t & 31, wid = t >> 5;
    const int v = (i < n) ? g_cnt[i] : 0;
    if (i < n) g_cnt[i] = 0;
    int x = v;
#pragma unroll
    for (int d = 1; d < 32; d <<= 1) {
        int y = __shfl_up_sync(~0u, x, d);
        if (lane >= d) x += y;
    }
    if (lane == 31) wsum[wid] = x;
    __syncthreads();
    if (wid == 0) {
        int s = wsum[lane];
#pragma unroll
        for (int d = 1; d < 32; d <<= 1) {
            int y = __shfl_up_sync(~0u, s, d);
            if (lane >= d) s += y;
        }
        wsum[lane] = s;
    }
    __syncthreads();
    const int excl = x - v + (wid > 0 ? wsum[wid - 1] : 0);
    if (i < n) g_off[i] = excl;
    if (t == 1023) g_bsum[blockIdx.x] = excl + v;
}
__global__ void scan_bsum_kernel(int nb)
{
    const int t = threadIdx.x;            // 128 threads, 4 warps
    __shared__ int wsum[4];
    const int lane = t & 31, wid = t >> 5;
    const int v = (t < nb) ? g_bsum[t] : 0;
    int x = v;
#pragma unroll
    for (int d = 1; d < 32; d <<= 1) {
        int y = __shfl_up_sync(~0u, x, d);
        if (lane >= d) x += y;
    }
    if (lane == 31) wsum[wid] = x;
    __syncthreads();
    int base = 0;
#pragma unroll
    for (int wj = 0; wj < 4; wj++)
        if (wj < wid) base += wsum[wj];
    if (t < nb) g_bsum[t] = x - v + base;   // exclusive
}
__global__ void scan_add_kernel(int n)
{
    int i = blockIdx.x * blockDim.x + threadIdx.x;
    if (i < n) {
        const int off = g_off[i] + g_bsum[i >> 10];
        g_off[i] = off;
        g_pos[i] = off;
    }
}
__global__ void scatter_kernel(const int* __restrict__ src,
                               const int* __restrict__ dst,
                               const int* __restrict__ rel, int n_edges)
{
    int i = blockIdx.x * blockDim.x + threadIdx.x;
    if (i >= n_edges) return;
    const int pos = atomicAdd(&g_pos[dst[i]], 1);
    g_pk[pos] = (src[i] << 3) | rel[i];
}

// ---------------- kernel 1: fp16 mma GEMM (256 thr, A-resident, ct-loop) ----------------
#define PADH 136
#define TILE_H (128 * PADH)
#define SM_TOTALB (3 * TILE_H * 2)    // 104448 B

__global__ void __launch_bounds__(256, 2)
rgcn_gemm_mma_kernel(const float* __restrict__ h,
                     const float* __restrict__ bias,
                     float* __restrict__ out, int n_nodes)
{
    extern __shared__ __half smemh[];
    __half* As = smemh;

    const int tid  = threadIdx.x;
    const int lane = tid & 31;
    const int w    = tid >> 5;
    const int g    = lane >> 2;
    const int tig  = lane & 3;
    const int warp_m = w & 3;
    const int warp_n = w >> 2;

    const int row0 = blockIdx.x * 128;

    const int l_row = lane & 15;
    const int l_kd  = (lane >> 4) * 8;

    const u32 sA = smem_u32(As);
    const u32 sB0 = sA + TILE_H * 2;
    const u32 sB1 = sA + 2 * TILE_H * 2;

#pragma unroll
    for (int i = 0; i < 16; i++) {
        const int v  = tid + i * 256;
        const int r  = v >> 5;
        const int c4 = (v & 31) * 4;
        float4 av = make_float4(0.f, 0.f, 0.f, 0.f);
        const int gr = row0 + r;
        if (gr < n_nodes)
            av = *(const float4*)(h + (size_t)gr * FEAT + c4);
        __half2 a01 = __floats2half2_rn(av.x, av.y);
        __half2 a23 = __floats2half2_rn(av.z, av.w);
        *(uint2*)(As + r * PADH + c4) = make_uint2(*(u32*)&a01, *(u32*)&a23);
    }

    auto issue_b = [&](int ct, u32 sBdst) {
        const __half* __restrict__ src = g_wth + (size_t)ct * FEAT * FEAT;
#pragma unroll
        for (int i = 0; i < 8; i++) {
            const int v  = tid + i * 256;
            const int r  = v >> 4;
            const int c8 = (v & 15) * 8;
            cpa16(sBdst + (u32)((r * PADH + c8) * 2), src + (size_t)r * FEAT + c8);
        }
        CPA_COMMIT();
    };

    issue_b(0, sB0);

    float acc[2][8][4];
#pragma unroll
    for (int mi = 0; mi < 2; mi++)
#pragma unroll
        for (int j = 0; j < 8; j++)
#pragma unroll
            for (int c = 0; c < 4; c++) acc[mi][j][c] = 0.f;

#pragma unroll 1
    for (int ct = 0; ct < NCT; ct++) {
        if (ct + 1 < NCT) {
            issue_b(ct + 1, ((ct + 1) & 1) ? sB1 : sB0);
            CPA_WAIT(1);
        } else {
            CPA_WAIT(0);
        }
        __syncthreads();
        const u32 sB = (ct & 1) ? sB1 : sB0;

#pragma unroll
        for (int ks = 0; ks < 8; ks++) {
            const int kk = ks * 16;
            u32 af[2][4];
#pragma unroll
            for (int mi = 0; mi < 2; mi++) {
                const u32 off = (u32)(((warp_m * 32 + mi * 16 + l_row) * PADH
                                       + kk + l_kd) * 2);
                ldsm4(af[mi][0], af[mi][1], af[mi][2], af[mi][3], sA + off);
            }
            u32 bf[8][2];
#pragma unroll
            for (int jp = 0; jp < 4; jp++) {
                const u32 off = (u32)(((warp_n * 64 + jp * 16 + l_row) * PADH
                                       + kk + l_kd) * 2);
                u32 m0, m1, m2, m3;
                ldsm4(m0, m1, m2, m3, sB + off);
                bf[2 * jp][0] = m0;     bf[2 * jp][1] = m2;
                bf[2 * jp + 1][0] = m1; bf[2 * jp + 1][1] = m3;
            }
#pragma unroll
            for (int mi = 0; mi < 2; mi++)
#pragma unroll
                for (int j = 0; j < 8; j++)
                    mma_f16(acc[mi][j], af[mi], bf[j]);
        }
        __syncthreads();

#pragma unroll
        for (int mi = 0; mi < 2; mi++) {
#pragma unroll
            for (int half = 0; half < 2; half++) {
                const int grow = row0 + warp_m * 32 + mi * 16 + g + half * 8;
                if (grow < n_nodes) {
                    if (ct < NUM_BASES) {
                        __half* p = g_projh + (size_t)grow * PROJ_STRIDE + ct * FEAT
                                  + warp_n * 64 + 2 * tig;
#pragma unroll
                        for (int j = 0; j < 8; j++)
                            *(__half2*)(p + 8 * j) =
                                __floats2half2_rn(acc[mi][j][2 * half],
                                                  acc[mi][j][2 * half + 1]);
                    } else {
                        float* p = out + (size_t)grow * FEAT + warp_n * 64 + 2 * tig;
#pragma unroll
                        for (int j = 0; j < 8; j++) {
                            const float2 b =
                                *(const float2*)(bias + warp_n * 64 + 2 * tig + 8 * j);
                            *(float2*)(p + 8 * j) =
                                make_float2(acc[mi][j][2 * half] + b.x,
                                            acc[mi][j][2 * half + 1] + b.y);
                        }
                    }
                }
            }
        }
#pragma unroll
        for (int mi = 0; mi < 2; mi++)
#pragma unroll
            for (int j = 0; j < 8; j++)
#pragma unroll
                for (int c = 0; c < 4; c++) acc[mi][j][c] = 0.f;
    }
}

// ---------------- kernel 2: warp-per-dst aggregation, atomic-free, fused ReLU ----------------
__global__ void __launch_bounds__(256)
rgcn_agg_kernel(const float* __restrict__ w_comp,
                float* __restrict__ out, int n_nodes)
{
    const int node = (blockIdx.x * blockDim.x + threadIdx.x) >> 5;
    const int lane = threadIdx.x & 31;
    if (node >= n_nodes) return;

    const int beg = g_off[node];
    const int end = g_off[node + 1];

    float* __restrict__ orow = out + (size_t)node * FEAT;
    float4 a = *(float4*)(orow + 4 * lane);   // root + bias from GEMM

    int e = beg;
    for (; e + 2 <= end; e += 2) {
        const int pk0 = g_pk[e], pk1 = g_pk[e + 1];
        const uint2* __restrict__ p0 =
            (const uint2*)(g_projh + (size_t)(pk0 >> 3) * PROJ_STRIDE) + lane;
        const uint2* __restrict__ p1 =
            (const uint2*)(g_projh + (size_t)(pk1 >> 3) * PROJ_STRIDE) + lane;
        const float4 c0 = *(const float4*)(w_comp + (pk0 & 7) * NUM_BASES);
        const float4 c1 = *(const float4*)(w_comp + (pk1 & 7) * NUM_BASES);
        uint2 r0[4], r1[4];
#pragma unroll
        for (int b = 0; b < 4; b++) { r0[b] = p0[b * 32]; r1[b] = p1[b * 32]; }
#pragma unroll
        for (int b = 0; b < 4; b++) {
            const float cb0 = (&c0.x)[b];
            const float2 u0 = __half22float2(*(const __half2*)&r0[b].x);
            const float2 u1 = __half22float2(*(const __half2*)&r0[b].y);
            a.x = fmaf(cb0, u0.x, a.x);
            a.y = fmaf(cb0, u0.y, a.y);
            a.z = fmaf(cb0, u1.x, a.z);
            a.w = fmaf(cb0, u1.y, a.w);
            const float cb1 = (&c1.x)[b];
            const float2 v0 = __half22float2(*(const __half2*)&r1[b].x);
            const float2 v1 = __half22float2(*(const __half2*)&r1[b].y);
            a.x = fmaf(cb1, v0.x, a.x);
            a.y = fmaf(cb1, v0.y, a.y);
            a.z = fmaf(cb1, v1.x, a.z);
            a.w = fmaf(cb1, v1.y, a.w);
        }
    }
    if (e < end) {
        const int pk = g_pk[e];
        const uint2* __restrict__ p =
            (const uint2*)(g_projh + (size_t)(pk >> 3) * PROJ_STRIDE) + lane;
        const float4 c = *(const float4*)(w_comp + (pk & 7) * NUM_BASES);
#pragma unroll
        for (int b = 0; b < 4; b++) {
            const float cb = (&c.x)[b];
            const uint2 raw = p[b * 32];
            const float2 u0 = __half22float2(*(const __half2*)&raw.x);
            const float2 u1 = __half22float2(*(const __half2*)&raw.y);
            a.x = fmaf(cb, u0.x, a.x);
            a.y = fmaf(cb, u0.y, a.y);
            a.z = fmaf(cb, u1.x, a.z);
            a.w = fmaf(cb, u1.y, a.w);
        }
    }

    a.x = fmaxf(a.x, 0.f); a.y = fmaxf(a.y, 0.f);
    a.z = fmaxf(a.z, 0.f); a.w = fmaxf(a.w, 0.f);
    *(float4*)(orow + 4 * lane) = a;
}

extern "C" void kernel_launch(void* const* d_in, const int* in_sizes, int n_in,
                              void* d_out, int out_size)
{
    const float* h      = (const float*)d_in[0];
    const float* weight = (const float*)d_in[1];
    const float* w_comp = (const float*)d_in[2];
    const float* root   = (const float*)d_in[3];
    const float* bias   = (const float*)d_in[4];
    const int*   src    = (const int*)d_in[5];
    const int*   dst    = (const int*)d_in[6];
    const int*   rel    = (const int*)d_in[7];

    const int n_nodes = in_sizes[0] / FEAT;
    const int n_edges = in_sizes[5];
    const int n_scan  = n_nodes + 1;
    const int n_chunk = (n_scan + 1023) / 1024;
    float* out = (float*)d_out;

    // one-time infra (host-side objects; no device allocations)
    static cudaStream_t s_side = nullptr;
    static cudaEvent_t  ev_fork = nullptr, ev_join = nullptr;
    static bool use_side = false;
    if (!s_side) {
        cudaError_t e1 = cudaStreamCreateWithFlags(&s_side, cudaStreamNonBlocking);
        cudaError_t e2 = cudaEventCreateWithFlags(&ev_fork, cudaEventDisableTiming);
        cudaError_t e3 = cudaEventCreateWithFlags(&ev_join, cudaEventDisableTiming);
        use_side = (e1 == cudaSuccess && e2 == cudaSuccess && e3 == cudaSuccess);
    }

    cudaFuncSetAttribute(rgcn_gemm_mma_kernel,
                         cudaFuncAttributeMaxDynamicSharedMemorySize, SM_TOTALB);

    cudaStream_t sc = use_side ? s_side : (cudaStream_t)0;

    // fork: CSR build on side stream, overlapping transpose + GEMM
    if (use_side) {
        cudaEventRecord(ev_fork, 0);
        cudaStreamWaitEvent(s_side, ev_fork, 0);
    }
    hist_kernel<<<(n_edges + 255) / 256, 256, 0, sc>>>(dst, n_edges);
    scan_chunk_kernel<<<n_chunk, 1024, 0, sc>>>(n_scan);
    scan_bsum_kernel<<<1, 128, 0, sc>>>(n_chunk);
    scan_add_kernel<<<(n_scan + 255) / 256, 256, 0, sc>>>(n_scan);
    scatter_kernel<<<(n_edges + 255) / 256, 256, 0, sc>>>(src, dst, rel, n_edges);
    if (use_side) cudaEventRecord(ev_join, s_side);

    // main stream: transpose + GEMM
    dim3 gt(4, 4, NCT);
    transpose_w_kernel<<<gt, dim3(32, 8)>>>(weight, root);
    rgcn_gemm_mma_kernel<<<(n_nodes + 127) / 128, 256, SM_TOTALB>>>(h, bias, out, n_nodes);

    // join, then aggregation + fused ReLU
    if (use_side) cudaStreamWaitEvent((cudaStream_t)0, ev_join, 0);
    rgcn_agg_kernel<<<(n_nodes + 7) / 8, 256>>>(w_comp, out, n_nodes);
}